// round 5
// baseline (speedup 1.0000x reference)
#include <cuda_runtime.h>
#include <cuda_fp16.h>
#include <cstdint>

#define BATCH 8
#define CCH   64
#define DQ    8
#define NPIX  4096
#define TM    128
#define TN    128
#define NT    (NPIX / TN)
#define NSPLIT 2
#define NT_S  (NT / NSPLIT)
#define L2E   1.4426950408889634f

__device__ __half g_q16[BATCH * NPIX * DQ];                 // pre-scaled by log2(e)
__device__ __half g_k16[BATCH * NPIX * DQ];
__device__ float  g_qn[BATCH * NPIX];
__device__ __half g_v16[(size_t)BATCH * CCH * NPIX];        // [b][c][n]
__device__ float  g_kmax_part[BATCH * 32];
__device__ float  g_pacc[NSPLIT][BATCH * 32][128][64];      // per-split partial acc
__device__ float  g_pls[NSPLIT][BATCH * 32][128][4];        // per-split partial lsum
__device__ int    g_ctr[BATCH * 32];

__device__ __forceinline__ uint32_t s2u(const void* p) {
    uint32_t a;
    asm("{ .reg .u64 t; cvta.to.shared.u64 t, %1; cvt.u32.u64 %0, t; }" : "=r"(a) : "l"(p));
    return a;
}
#define CP16(dst, src) asm volatile("cp.async.cg.shared.global [%0], [%1], 16;" :: "r"(dst), "l"(src) : "memory")
#define CPCOMMIT()     asm volatile("cp.async.commit_group;" ::: "memory")
#define CPWAIT1()      asm volatile("cp.async.wait_group 1;" ::: "memory")
#define CPWAIT0()      asm volatile("cp.async.wait_group 0;" ::: "memory")

// ---------------------------------------------------------------------------
// QKV projection (128 thr, grid (32, B)). Also resets combine counters.
// ---------------------------------------------------------------------------
__global__ __launch_bounds__(128) void qkv_kernel(
    const float* __restrict__ x,
    const float* __restrict__ wq, const float* __restrict__ bq,
    const float* __restrict__ wk, const float* __restrict__ bk,
    const float* __restrict__ wv, const float* __restrict__ bv)
{
    __shared__ float swq[DQ * CCH], swk[DQ * CCH], swv[CCH * CCH];
    __shared__ float sbq[DQ], sbk[DQ], sbv[CCH];
    __shared__ float swmax[4];

    const int tid = threadIdx.x;
    const int b = blockIdx.y;
    if (blockIdx.x == 0 && tid < 32) g_ctr[b * 32 + tid] = 0;

    for (int i = tid; i < DQ * CCH; i += 128) { swq[i] = wq[i]; swk[i] = wk[i]; }
    for (int i = tid; i < CCH * CCH; i += 128) swv[i] = wv[i];
    if (tid < DQ) { sbq[tid] = bq[tid]; sbk[tid] = bk[tid]; }
    if (tid < CCH) sbv[tid] = bv[tid];
    __syncthreads();

    const int n = blockIdx.x * 128 + tid;

    float xv[CCH];
    const float* xb = x + ((size_t)b * CCH) * NPIX + n;
    #pragma unroll
    for (int c = 0; c < CCH; c++) xv[c] = xb[(size_t)c * NPIX];

    float qv[DQ], kv[DQ];
    #pragma unroll
    for (int d = 0; d < DQ; d++) {
        float aq = sbq[d], ak = sbk[d];
        #pragma unroll
        for (int c = 0; c < CCH; c++) {
            aq = fmaf(swq[d * CCH + c], xv[c], aq);
            ak = fmaf(swk[d * CCH + c], xv[c], ak);
        }
        qv[d] = aq; kv[d] = ak;
    }
    {
        __half2* qo = (__half2*)&g_q16[((size_t)b * NPIX + n) * DQ];
        __half2* ko = (__half2*)&g_k16[((size_t)b * NPIX + n) * DQ];
        #pragma unroll
        for (int d = 0; d < 4; d++) {
            qo[d] = __floats2half2_rn(qv[2*d] * L2E, qv[2*d+1] * L2E);
            ko[d] = __floats2half2_rn(kv[2*d], kv[2*d+1]);
        }
    }
    {
        float nq2 = 0.f, nk2 = 0.f;
        #pragma unroll
        for (int d = 0; d < DQ; d++) {
            nq2 = fmaf(qv[d], qv[d], nq2);
            nk2 = fmaf(kv[d], kv[d], nk2);
        }
        g_qn[b * NPIX + n] = sqrtf(nq2);
        float nk = sqrtf(nk2);
        #pragma unroll
        for (int off = 16; off > 0; off >>= 1)
            nk = fmaxf(nk, __shfl_xor_sync(0xFFFFFFFFu, nk, off));
        if ((tid & 31) == 0) swmax[tid >> 5] = nk;
        __syncthreads();
        if (tid == 0)
            g_kmax_part[b * 32 + blockIdx.x] =
                fmaxf(fmaxf(swmax[0], swmax[1]), fmaxf(swmax[2], swmax[3]));
    }
    #pragma unroll 4
    for (int o = 0; o < CCH; o += 4) {
        float a0 = sbv[o+0], a1 = sbv[o+1], a2 = sbv[o+2], a3 = sbv[o+3];
        #pragma unroll
        for (int c = 0; c < CCH; c++) {
            float xc = xv[c];
            a0 = fmaf(swv[(o+0)*CCH + c], xc, a0);
            a1 = fmaf(swv[(o+1)*CCH + c], xc, a1);
            a2 = fmaf(swv[(o+2)*CCH + c], xc, a2);
            a3 = fmaf(swv[(o+3)*CCH + c], xc, a3);
        }
        g_v16[((size_t)(b*CCH + o+0))*NPIX + n] = __float2half_rn(a0);
        g_v16[((size_t)(b*CCH + o+1))*NPIX + n] = __float2half_rn(a1);
        g_v16[((size_t)(b*CCH + o+2))*NPIX + n] = __float2half_rn(a2);
        g_v16[((size_t)(b*CCH + o+3))*NPIX + n] = __float2half_rn(a3);
    }
}

// ---------------------------------------------------------------------------
// Flash attention, split-N x2, all-HMMA, last-CTA combine.
// Grid (NSPLIT, 32, 8), 128 threads (4 warps); warp owns 32 m-rows.
// ---------------------------------------------------------------------------
#define STAGE(t, buf) do { \
    const __half* _ks = g_k16 + ((size_t)b * NPIX + (t) * TN + tid) * DQ; \
    CP16(s2u(&sK[buf][tid][0]), _ks); \
    _Pragma("unroll") \
    for (int _i = 0; _i < 8; _i++) { \
        int _l = _i * 128 + tid, _row = _l >> 4, _seg = _l & 15; \
        const __half* _vs = g_v16 + ((size_t)(b * CCH + _row)) * NPIX + (t) * TN + _seg * 8; \
        CP16(s2u(&sV[buf][_row][_seg * 8]), _vs); \
    } \
} while (0)

__global__ __launch_bounds__(128) void attn_kernel(
    const float* __restrict__ x,
    const float* __restrict__ gamma,
    float* __restrict__ out)
{
    __shared__ __align__(16) __half sK[2][TN][24];
    __shared__ __align__(16) __half sV[2][CCH][136];
    __shared__ int s_old;

    const int tid  = threadIdx.x;
    const int w    = tid >> 5;
    const int lane = tid & 31;
    const int g    = lane >> 2;
    const int c    = lane & 3;
    const int split= blockIdx.x;
    const int mblk = blockIdx.y;
    const int b    = blockIdx.z;
    const int m0   = mblk * TM + w * 32;

    float kmax = g_kmax_part[b * 32];
    #pragma unroll
    for (int i = 1; i < 32; i++) kmax = fmaxf(kmax, g_kmax_part[b * 32 + i]);

    uint32_t qa0[2], qa1[2];
    float nsh[4];
    #pragma unroll
    for (int mt = 0; mt < 2; mt++) {
        const int rA = m0 + mt * 16 + g, rB = rA + 8;
        qa0[mt] = *(const uint32_t*)&g_q16[((size_t)b * NPIX + rA) * DQ + 2 * c];
        qa1[mt] = *(const uint32_t*)&g_q16[((size_t)b * NPIX + rB) * DQ + 2 * c];
        nsh[2*mt]   = -g_qn[b * NPIX + rA] * kmax * L2E;
        nsh[2*mt+1] = -g_qn[b * NPIX + rB] * kmax * L2E;
    }

    float acc[2][8][4];
    #pragma unroll
    for (int mt = 0; mt < 2; mt++)
        #pragma unroll
        for (int jc = 0; jc < 8; jc++)
            #pragma unroll
            for (int r = 0; r < 4; r++) acc[mt][jc][r] = 0.f;
    float ls[4] = {0.f, 0.f, 0.f, 0.f};

    const int tb = split * NT_S;
    STAGE(tb, 0); CPCOMMIT();

    #pragma unroll 1
    for (int tt = 0; tt < NT_S; tt++) {
        if (tt + 1 < NT_S) { STAGE(tb + tt + 1, (tt + 1) & 1); CPCOMMIT(); CPWAIT1(); }
        else               { CPWAIT0(); }
        __syncthreads();
        const __half (*K)[24]  = sK[tt & 1];
        const __half (*V)[136] = sV[tt & 1];

        #pragma unroll
        for (int kc = 0; kc < 8; kc++) {
            const uint32_t kb0 = *(const uint32_t*)&K[kc * 16 + g][2 * c];
            const uint32_t kb1 = *(const uint32_t*)&K[kc * 16 + 8 + g][2 * c];
            uint32_t pf[2][4];
            #pragma unroll
            for (int mt = 0; mt < 2; mt++) {
                float s0, s1, s2, s3;
                asm volatile(
                    "mma.sync.aligned.m16n8k8.row.col.f32.f16.f16.f32 "
                    "{%0,%1,%2,%3},{%4,%5},{%6},{%7,%8,%9,%10};"
                    : "=f"(s0), "=f"(s1), "=f"(s2), "=f"(s3)
                    : "r"(qa0[mt]), "r"(qa1[mt]), "r"(kb0),
                      "f"(nsh[2*mt]), "f"(nsh[2*mt]), "f"(nsh[2*mt+1]), "f"(nsh[2*mt+1]));
                uint32_t u0, u1;
                asm("cvt.rn.f16x2.f32 %0, %1, %2;" : "=r"(u0) : "f"(s1), "f"(s0));
                asm("cvt.rn.f16x2.f32 %0, %1, %2;" : "=r"(u1) : "f"(s3), "f"(s2));
                asm("ex2.approx.f16x2 %0, %1;" : "=r"(pf[mt][0]) : "r"(u0));
                asm("ex2.approx.f16x2 %0, %1;" : "=r"(pf[mt][1]) : "r"(u1));
                asm volatile(
                    "mma.sync.aligned.m16n8k8.row.col.f32.f16.f16.f32 "
                    "{%0,%1,%2,%3},{%4,%5},{%6},{%7,%8,%9,%10};"
                    : "=f"(s0), "=f"(s1), "=f"(s2), "=f"(s3)
                    : "r"(qa0[mt]), "r"(qa1[mt]), "r"(kb1),
                      "f"(nsh[2*mt]), "f"(nsh[2*mt]), "f"(nsh[2*mt+1]), "f"(nsh[2*mt+1]));
                asm("cvt.rn.f16x2.f32 %0, %1, %2;" : "=r"(u0) : "f"(s1), "f"(s0));
                asm("cvt.rn.f16x2.f32 %0, %1, %2;" : "=r"(u1) : "f"(s3), "f"(s2));
                asm("ex2.approx.f16x2 %0, %1;" : "=r"(pf[mt][2]) : "r"(u0));
                asm("ex2.approx.f16x2 %0, %1;" : "=r"(pf[mt][3]) : "r"(u1));
            }
            // lsum on alu/fma pipes (tensor pipe is the bottleneck)
            #pragma unroll
            for (int mt = 0; mt < 2; mt++) {
                __half2 hA = __hadd2(*(__half2*)&pf[mt][0], *(__half2*)&pf[mt][2]);
                __half2 hB = __hadd2(*(__half2*)&pf[mt][1], *(__half2*)&pf[mt][3]);
                float2 fA = __half22float2(hA);
                float2 fB = __half22float2(hB);
                ls[2*mt]   += fA.x + fA.y;
                ls[2*mt+1] += fB.x + fB.y;
            }
            // PV: 8 V-channel tiles
            #pragma unroll
            for (int jc = 0; jc < 8; jc++) {
                const uint32_t b0 = *(const uint32_t*)&V[jc * 8 + g][kc * 16 + 2 * c];
                const uint32_t b1 = *(const uint32_t*)&V[jc * 8 + g][kc * 16 + 2 * c + 8];
                #pragma unroll
                for (int mt = 0; mt < 2; mt++) {
                    asm volatile(
                        "mma.sync.aligned.m16n8k16.row.col.f32.f16.f16.f32 "
                        "{%0,%1,%2,%3},{%4,%5,%6,%7},{%8,%9},{%0,%1,%2,%3};"
                        : "+f"(acc[mt][jc][0]), "+f"(acc[mt][jc][1]),
                          "+f"(acc[mt][jc][2]), "+f"(acc[mt][jc][3])
                        : "r"(pf[mt][0]), "r"(pf[mt][1]), "r"(pf[mt][2]), "r"(pf[mt][3]),
                          "r"(b0), "r"(b1));
                }
            }
        }
        __syncthreads();
    }

    // quad-reduce lsum (all lanes end with full row sums)
    #pragma unroll
    for (int i = 0; i < 4; i++) {
        ls[i] += __shfl_xor_sync(0xFFFFFFFFu, ls[i], 1);
        ls[i] += __shfl_xor_sync(0xFFFFFFFFu, ls[i], 2);
    }

    // publish partials
    const int reg = b * 32 + mblk;
    {
        float4* pa = (float4*)&g_pacc[split][reg][tid][0];
        #pragma unroll
        for (int mt = 0; mt < 2; mt++)
            #pragma unroll
            for (int jc = 0; jc < 8; jc++)
                pa[mt * 8 + jc] = make_float4(acc[mt][jc][0], acc[mt][jc][1],
                                              acc[mt][jc][2], acc[mt][jc][3]);
        *(float4*)&g_pls[split][reg][tid][0] = make_float4(ls[0], ls[1], ls[2], ls[3]);
    }
    __threadfence();
    if (tid == 0) s_old = atomicAdd(&g_ctr[reg], 1);
    __syncthreads();
    if (s_old == 0) return;   // first finisher: peer will combine

    // combine with peer split
    {
        const float4* pa = (const float4*)&g_pacc[1 - split][reg][tid][0];
        #pragma unroll
        for (int mt = 0; mt < 2; mt++)
            #pragma unroll
            for (int jc = 0; jc < 8; jc++) {
                float4 v = pa[mt * 8 + jc];
                acc[mt][jc][0] += v.x; acc[mt][jc][1] += v.y;
                acc[mt][jc][2] += v.z; acc[mt][jc][3] += v.w;
            }
        float4 pl = *(const float4*)&g_pls[1 - split][reg][tid][0];
        ls[0] += pl.x; ls[1] += pl.y; ls[2] += pl.z; ls[3] += pl.w;
    }

    const float gm = gamma[0];
    const float* xb = x   + (size_t)b * CCH * NPIX;
    float*       ob = out + (size_t)b * CCH * NPIX;
    #pragma unroll
    for (int mt = 0; mt < 2; mt++) {
        const float iA = 1.f / ls[2*mt], iB = 1.f / ls[2*mt+1];
        const int rA = m0 + mt * 16 + g, rB = rA + 8;
        #pragma unroll
        for (int jc = 0; jc < 8; jc++) {
            const int ch0 = jc * 8 + 2 * c, ch1 = ch0 + 1;
            ob[(size_t)ch0 * NPIX + rA] = fmaf(gm, acc[mt][jc][0] * iA, xb[(size_t)ch0 * NPIX + rA]);
            ob[(size_t)ch1 * NPIX + rA] = fmaf(gm, acc[mt][jc][1] * iA, xb[(size_t)ch1 * NPIX + rA]);
            ob[(size_t)ch0 * NPIX + rB] = fmaf(gm, acc[mt][jc][2] * iB, xb[(size_t)ch0 * NPIX + rB]);
            ob[(size_t)ch1 * NPIX + rB] = fmaf(gm, acc[mt][jc][3] * iB, xb[(size_t)ch1 * NPIX + rB]);
        }
    }
}

// ---------------------------------------------------------------------------
extern "C" void kernel_launch(void* const* d_in, const int* in_sizes, int n_in,
                              void* d_out, int out_size)
{
    const float* x     = (const float*)d_in[0];
    const float* wq    = (const float*)d_in[1];
    const float* bq    = (const float*)d_in[2];
    const float* wk    = (const float*)d_in[3];
    const float* bk    = (const float*)d_in[4];
    const float* wv    = (const float*)d_in[5];
    const float* bv    = (const float*)d_in[6];
    const float* gamma = (const float*)d_in[7];
    float* out = (float*)d_out;

    dim3 g1(NPIX / 128, BATCH);
    qkv_kernel<<<g1, 128>>>(x, wq, bq, wk, bk, wv, bv);
    dim3 g2(NSPLIT, NPIX / TM, BATCH);
    attn_kernel<<<g2, TM>>>(x, gamma, out);
}

// round 6
// speedup vs baseline: 1.0043x; 1.0043x over previous
#include <cuda_runtime.h>
#include <cuda_fp16.h>
#include <cstdint>

#define BATCH 8
#define CCH   64
#define DQ    8
#define NPIX  4096
#define TM    128
#define TN    128
#define NT    (NPIX / TN)
#define L2E   1.4426950408889634f

__device__ __half g_q16[BATCH * NPIX * DQ];                 // pre-scaled by log2(e)
__device__ __half g_k16[BATCH * NPIX * DQ];
__device__ float  g_qn[BATCH * NPIX];
__device__ __half g_v16[(size_t)BATCH * CCH * NPIX];        // [b][c][n]
__device__ float  g_kmax_part[BATCH * 32];

__device__ __forceinline__ uint32_t s2u(const void* p) {
    uint32_t a;
    asm("{ .reg .u64 t; cvta.to.shared.u64 t, %1; cvt.u32.u64 %0, t; }" : "=r"(a) : "l"(p));
    return a;
}
#define CP16(dst, src) asm volatile("cp.async.cg.shared.global [%0], [%1], 16;" :: "r"(dst), "l"(src) : "memory")
#define CPCOMMIT()     asm volatile("cp.async.commit_group;" ::: "memory")
#define CPWAIT1()      asm volatile("cp.async.wait_group 1;" ::: "memory")
#define CPWAIT0()      asm volatile("cp.async.wait_group 0;" ::: "memory")

// ---------------------------------------------------------------------------
// QKV projection (128 thr, grid (32, B)).
// ---------------------------------------------------------------------------
__global__ __launch_bounds__(128) void qkv_kernel(
    const float* __restrict__ x,
    const float* __restrict__ wq, const float* __restrict__ bq,
    const float* __restrict__ wk, const float* __restrict__ bk,
    const float* __restrict__ wv, const float* __restrict__ bv)
{
    __shared__ float swq[DQ * CCH], swk[DQ * CCH], swv[CCH * CCH];
    __shared__ float sbq[DQ], sbk[DQ], sbv[CCH];
    __shared__ float swmax[4];

    const int tid = threadIdx.x;
    const int b = blockIdx.y;

    for (int i = tid; i < DQ * CCH; i += 128) { swq[i] = wq[i]; swk[i] = wk[i]; }
    for (int i = tid; i < CCH * CCH; i += 128) swv[i] = wv[i];
    if (tid < DQ) { sbq[tid] = bq[tid]; sbk[tid] = bk[tid]; }
    if (tid < CCH) sbv[tid] = bv[tid];
    __syncthreads();

    const int n = blockIdx.x * 128 + tid;

    float xv[CCH];
    const float* xb = x + ((size_t)b * CCH) * NPIX + n;
    #pragma unroll
    for (int c = 0; c < CCH; c++) xv[c] = xb[(size_t)c * NPIX];

    float qv[DQ], kv[DQ];
    #pragma unroll
    for (int d = 0; d < DQ; d++) {
        float aq = sbq[d], ak = sbk[d];
        #pragma unroll
        for (int c = 0; c < CCH; c++) {
            aq = fmaf(swq[d * CCH + c], xv[c], aq);
            ak = fmaf(swk[d * CCH + c], xv[c], ak);
        }
        qv[d] = aq; kv[d] = ak;
    }
    {
        __half2* qo = (__half2*)&g_q16[((size_t)b * NPIX + n) * DQ];
        __half2* ko = (__half2*)&g_k16[((size_t)b * NPIX + n) * DQ];
        #pragma unroll
        for (int d = 0; d < 4; d++) {
            qo[d] = __floats2half2_rn(qv[2*d] * L2E, qv[2*d+1] * L2E);
            ko[d] = __floats2half2_rn(kv[2*d], kv[2*d+1]);
        }
    }
    {
        float nq2 = 0.f, nk2 = 0.f;
        #pragma unroll
        for (int d = 0; d < DQ; d++) {
            nq2 = fmaf(qv[d], qv[d], nq2);
            nk2 = fmaf(kv[d], kv[d], nk2);
        }
        g_qn[b * NPIX + n] = sqrtf(nq2);
        float nk = sqrtf(nk2);
        #pragma unroll
        for (int off = 16; off > 0; off >>= 1)
            nk = fmaxf(nk, __shfl_xor_sync(0xFFFFFFFFu, nk, off));
        if ((tid & 31) == 0) swmax[tid >> 5] = nk;
        __syncthreads();
        if (tid == 0)
            g_kmax_part[b * 32 + blockIdx.x] =
                fmaxf(fmaxf(swmax[0], swmax[1]), fmaxf(swmax[2], swmax[3]));
    }
    #pragma unroll 4
    for (int o = 0; o < CCH; o += 4) {
        float a0 = sbv[o+0], a1 = sbv[o+1], a2 = sbv[o+2], a3 = sbv[o+3];
        #pragma unroll
        for (int c = 0; c < CCH; c++) {
            float xc = xv[c];
            a0 = fmaf(swv[(o+0)*CCH + c], xc, a0);
            a1 = fmaf(swv[(o+1)*CCH + c], xc, a1);
            a2 = fmaf(swv[(o+2)*CCH + c], xc, a2);
            a3 = fmaf(swv[(o+3)*CCH + c], xc, a3);
        }
        g_v16[((size_t)(b*CCH + o+0))*NPIX + n] = __float2half_rn(a0);
        g_v16[((size_t)(b*CCH + o+1))*NPIX + n] = __float2half_rn(a1);
        g_v16[((size_t)(b*CCH + o+2))*NPIX + n] = __float2half_rn(a2);
        g_v16[((size_t)(b*CCH + o+3))*NPIX + n] = __float2half_rn(a3);
    }
}

// ---------------------------------------------------------------------------
// Flash attention: all-HMMA, software-pipelined kc chunks (S of kc+1 overlaps
// PV of kc). Grid (32, 8), 128 threads (4 warps); warp owns 32 m-rows.
// ---------------------------------------------------------------------------
#define STAGE(t, buf) do { \
    const __half* _ks = g_k16 + ((size_t)b * NPIX + (t) * TN + tid) * DQ; \
    CP16(s2u(&sK[buf][tid][0]), _ks); \
    _Pragma("unroll") \
    for (int _i = 0; _i < 8; _i++) { \
        int _l = _i * 128 + tid, _row = _l >> 4, _seg = _l & 15; \
        const __half* _vs = g_v16 + ((size_t)(b * CCH + _row)) * NPIX + (t) * TN + _seg * 8; \
        CP16(s2u(&sV[buf][_row][_seg * 8]), _vs); \
    } \
} while (0)

// S-MMAs for chunk kc -> sv[2][8] (asm volatile pins issue order)
#define SMMA(K, kc, sv) do { \
    const uint32_t _kb0 = *(const uint32_t*)&(K)[(kc) * 16 + g][2 * c]; \
    const uint32_t _kb1 = *(const uint32_t*)&(K)[(kc) * 16 + 8 + g][2 * c]; \
    _Pragma("unroll") \
    for (int _mt = 0; _mt < 2; _mt++) { \
        asm volatile("mma.sync.aligned.m16n8k8.row.col.f32.f16.f16.f32 " \
            "{%0,%1,%2,%3},{%4,%5},{%6},{%7,%8,%9,%10};" \
            : "=f"((sv)[_mt][0]), "=f"((sv)[_mt][1]), "=f"((sv)[_mt][2]), "=f"((sv)[_mt][3]) \
            : "r"(qa0[_mt]), "r"(qa1[_mt]), "r"(_kb0), \
              "f"(nsh[2*_mt]), "f"(nsh[2*_mt]), "f"(nsh[2*_mt+1]), "f"(nsh[2*_mt+1])); \
        asm volatile("mma.sync.aligned.m16n8k8.row.col.f32.f16.f16.f32 " \
            "{%0,%1,%2,%3},{%4,%5},{%6},{%7,%8,%9,%10};" \
            : "=f"((sv)[_mt][4]), "=f"((sv)[_mt][5]), "=f"((sv)[_mt][6]), "=f"((sv)[_mt][7]) \
            : "r"(qa0[_mt]), "r"(qa1[_mt]), "r"(_kb1), \
              "f"(nsh[2*_mt]), "f"(nsh[2*_mt]), "f"(nsh[2*_mt+1]), "f"(nsh[2*_mt+1])); \
    } \
} while (0)

// cvt + ex2 for chunk -> pf[2][4]
#define EXPCVT(sv, pf) do { \
    _Pragma("unroll") \
    for (int _mt = 0; _mt < 2; _mt++) { \
        uint32_t _u0, _u1, _u2, _u3; \
        asm volatile("cvt.rn.f16x2.f32 %0, %1, %2;" : "=r"(_u0) : "f"((sv)[_mt][1]), "f"((sv)[_mt][0])); \
        asm volatile("cvt.rn.f16x2.f32 %0, %1, %2;" : "=r"(_u1) : "f"((sv)[_mt][3]), "f"((sv)[_mt][2])); \
        asm volatile("cvt.rn.f16x2.f32 %0, %1, %2;" : "=r"(_u2) : "f"((sv)[_mt][5]), "f"((sv)[_mt][4])); \
        asm volatile("cvt.rn.f16x2.f32 %0, %1, %2;" : "=r"(_u3) : "f"((sv)[_mt][7]), "f"((sv)[_mt][6])); \
        asm volatile("ex2.approx.f16x2 %0, %1;" : "=r"((pf)[_mt][0]) : "r"(_u0)); \
        asm volatile("ex2.approx.f16x2 %0, %1;" : "=r"((pf)[_mt][1]) : "r"(_u1)); \
        asm volatile("ex2.approx.f16x2 %0, %1;" : "=r"((pf)[_mt][2]) : "r"(_u2)); \
        asm volatile("ex2.approx.f16x2 %0, %1;" : "=r"((pf)[_mt][3]) : "r"(_u3)); \
    } \
} while (0)

// PV MMAs for chunk kc over jc in [jc0, jc1)
#define PVMMA(V, kc, jc0, jc1, pf) do { \
    _Pragma("unroll") \
    for (int _jc = (jc0); _jc < (jc1); _jc++) { \
        const uint32_t _b0 = *(const uint32_t*)&(V)[_jc * 8 + g][(kc) * 16 + 2 * c]; \
        const uint32_t _b1 = *(const uint32_t*)&(V)[_jc * 8 + g][(kc) * 16 + 2 * c + 8]; \
        _Pragma("unroll") \
        for (int _mt = 0; _mt < 2; _mt++) { \
            asm volatile("mma.sync.aligned.m16n8k16.row.col.f32.f16.f16.f32 " \
                "{%0,%1,%2,%3},{%4,%5,%6,%7},{%8,%9},{%0,%1,%2,%3};" \
                : "+f"(acc[_mt][_jc][0]), "+f"(acc[_mt][_jc][1]), \
                  "+f"(acc[_mt][_jc][2]), "+f"(acc[_mt][_jc][3]) \
                : "r"((pf)[_mt][0]), "r"((pf)[_mt][1]), "r"((pf)[_mt][2]), "r"((pf)[_mt][3]), \
                  "r"(_b0), "r"(_b1)); \
        } \
    } \
} while (0)

__global__ __launch_bounds__(128) void attn_kernel(
    const float* __restrict__ x,
    const float* __restrict__ gamma,
    float* __restrict__ out)
{
    __shared__ __align__(16) __half sK[2][TN][24];
    __shared__ __align__(16) __half sV[2][CCH][136];

    const int tid  = threadIdx.x;
    const int w    = tid >> 5;
    const int lane = tid & 31;
    const int g    = lane >> 2;
    const int c    = lane & 3;
    const int b    = blockIdx.y;
    const int m0   = blockIdx.x * TM + w * 32;

    float kmax = g_kmax_part[b * 32];
    #pragma unroll
    for (int i = 1; i < 32; i++) kmax = fmaxf(kmax, g_kmax_part[b * 32 + i]);

    uint32_t qa0[2], qa1[2];
    float nsh[4];
    #pragma unroll
    for (int mt = 0; mt < 2; mt++) {
        const int rA = m0 + mt * 16 + g, rB = rA + 8;
        qa0[mt] = *(const uint32_t*)&g_q16[((size_t)b * NPIX + rA) * DQ + 2 * c];
        qa1[mt] = *(const uint32_t*)&g_q16[((size_t)b * NPIX + rB) * DQ + 2 * c];
        nsh[2*mt]   = -g_qn[b * NPIX + rA] * kmax * L2E;
        nsh[2*mt+1] = -g_qn[b * NPIX + rB] * kmax * L2E;
    }

    float acc[2][8][4];
    #pragma unroll
    for (int mt = 0; mt < 2; mt++)
        #pragma unroll
        for (int jc = 0; jc < 8; jc++)
            #pragma unroll
            for (int r = 0; r < 4; r++) acc[mt][jc][r] = 0.f;
    float ls[4] = {0.f, 0.f, 0.f, 0.f};

    STAGE(0, 0); CPCOMMIT();

    #pragma unroll 1
    for (int t = 0; t < NT; t++) {
        if (t + 1 < NT) { STAGE(t + 1, (t + 1) & 1); CPCOMMIT(); CPWAIT1(); }
        else            { CPWAIT0(); }
        __syncthreads();
        const __half (*K)[24]  = sK[t & 1];
        const __half (*V)[136] = sV[t & 1];

        float sv[2][8];
        uint32_t pfc[2][4], pfn[2][4];
        SMMA(K, 0, sv);
        EXPCVT(sv, pfc);

        #pragma unroll
        for (int kc = 0; kc < 8; kc++) {
            if (kc < 7) SMMA(K, kc + 1, sv);       // S of next chunk queues first
            PVMMA(V, kc, 0, 4, pfc);               // PV(kc) first half overlaps S latency
            if (kc < 7) EXPCVT(sv, pfn);           // exp of next chunk
            PVMMA(V, kc, 4, 8, pfc);               // PV(kc) second half overlaps MUFU
            // lsum on alu/fma pipes
            #pragma unroll
            for (int mt = 0; mt < 2; mt++) {
                __half2 hA = __hadd2(*(__half2*)&pfc[mt][0], *(__half2*)&pfc[mt][2]);
                __half2 hB = __hadd2(*(__half2*)&pfc[mt][1], *(__half2*)&pfc[mt][3]);
                float2 fA = __half22float2(hA);
                float2 fB = __half22float2(hB);
                ls[2*mt]   += fA.x + fA.y;
                ls[2*mt+1] += fB.x + fB.y;
            }
            if (kc < 7) {
                #pragma unroll
                for (int mt = 0; mt < 2; mt++)
                    #pragma unroll
                    for (int r = 0; r < 4; r++) pfc[mt][r] = pfn[mt][r];
            }
        }
        __syncthreads();
    }

    // quad-reduce lsum
    #pragma unroll
    for (int i = 0; i < 4; i++) {
        ls[i] += __shfl_xor_sync(0xFFFFFFFFu, ls[i], 1);
        ls[i] += __shfl_xor_sync(0xFFFFFFFFu, ls[i], 2);
    }

    const float gm = gamma[0];
    const float* xb = x   + (size_t)b * CCH * NPIX;
    float*       ob = out + (size_t)b * CCH * NPIX;
    #pragma unroll
    for (int mt = 0; mt < 2; mt++) {
        const float iA = 1.f / ls[2*mt], iB = 1.f / ls[2*mt+1];
        const int rA = m0 + mt * 16 + g, rB = rA + 8;
        #pragma unroll
        for (int jc = 0; jc < 8; jc++) {
            const int ch0 = jc * 8 + 2 * c, ch1 = ch0 + 1;
            ob[(size_t)ch0 * NPIX + rA] = fmaf(gm, acc[mt][jc][0] * iA, xb[(size_t)ch0 * NPIX + rA]);
            ob[(size_t)ch1 * NPIX + rA] = fmaf(gm, acc[mt][jc][1] * iA, xb[(size_t)ch1 * NPIX + rA]);
            ob[(size_t)ch0 * NPIX + rB] = fmaf(gm, acc[mt][jc][2] * iB, xb[(size_t)ch0 * NPIX + rB]);
            ob[(size_t)ch1 * NPIX + rB] = fmaf(gm, acc[mt][jc][3] * iB, xb[(size_t)ch1 * NPIX + rB]);
        }
    }
}

// ---------------------------------------------------------------------------
extern "C" void kernel_launch(void* const* d_in, const int* in_sizes, int n_in,
                              void* d_out, int out_size)
{
    const float* x     = (const float*)d_in[0];
    const float* wq    = (const float*)d_in[1];
    const float* bq    = (const float*)d_in[2];
    const float* wk    = (const float*)d_in[3];
    const float* bk    = (const float*)d_in[4];
    const float* wv    = (const float*)d_in[5];
    const float* bv    = (const float*)d_in[6];
    const float* gamma = (const float*)d_in[7];
    float* out = (float*)d_out;

    dim3 g1(NPIX / 128, BATCH);
    qkv_kernel<<<g1, 128>>>(x, wq, bq, wk, bk, wv, bv);
    dim3 g2(NPIX / TM, BATCH);
    attn_kernel<<<g2, TM>>>(x, gamma, out);
}